// round 2
// baseline (speedup 1.0000x reference)
#include <cuda_runtime.h>
#include <math.h>

#define NTOT 32768
#define CDIM 256
#define KCODES 1024
#define HW 1024
#define BN 64
#define KT 256
#define CT 32
#define ZPITCH 68   // 64 + 4 pad, keeps 16B alignment, kills phase-2 column conflicts

// ---- output layout (flattened tuple, float32) ----
#define O_Q      0ull
#define O_LOSS   8388608ull
#define O_PERP   8388609ull
#define O_TOK    8388610ull
#define O_NCS    8421378ull
#define O_NEW_W  8422402ull   // == 2 (mod 4): NO float4 access on out here!
#define O_NEW_E  8684546ull   // == 2 (mod 4)

// ---- device scratch (no allocations allowed); force 16B alignment ----
__device__ __align__(16) float g_eT[CDIM * KCODES];   // [c][k]
__device__ __align__(16) float g_enorm[KCODES];
__device__ __align__(16) float g_counts[KCODES];
__device__ __align__(16) float g_dw[KCODES * CDIM];
__device__ __align__(16) float g_invcs[KCODES];
__device__ float g_loss;

// ---- packed f32x2 helpers ----
__device__ __forceinline__ void ffma2(unsigned long long& d,
                                      unsigned long long a,
                                      unsigned long long b) {
    asm("fma.rn.f32x2 %0, %1, %2, %0;" : "+l"(d) : "l"(a), "l"(b));
}
__device__ __forceinline__ unsigned long long packdup(float x) {
    unsigned long long r;
    asm("mov.b64 %0, {%1, %1};" : "=l"(r) : "f"(x));
    return r;
}
__device__ __forceinline__ void unpack2(unsigned long long v, float& lo, float& hi) {
    asm("mov.b64 {%0, %1}, %2;" : "=f"(lo), "=f"(hi) : "l"(v));
}

// ============================================================
// K0: eT transpose + ||e||^2 + zero scratch.  grid 1024 x 256
// ============================================================
__global__ void vq_prep(const float* __restrict__ emb) {
    int k = blockIdx.x, t = threadIdx.x;
    float v = emb[k * CDIM + t];
    g_eT[t * KCODES + k] = v;
    g_dw[k * CDIM + t] = 0.0f;
    float s = v * v;
    __shared__ float red[8];
    #pragma unroll
    for (int o = 16; o; o >>= 1) s += __shfl_xor_sync(~0u, s, o);
    if ((t & 31) == 0) red[t >> 5] = s;
    __syncthreads();
    if (t == 0) {
        float tot = 0.f;
        #pragma unroll
        for (int i = 0; i < 8; i++) tot += red[i];
        g_enorm[k] = tot;
        g_counts[k] = 0.0f;
        if (k == 0) g_loss = 0.0f;
    }
}

// ============================================================
// K1: argmin GEMM + fused epilogue.  grid 512 x 256, dyn smem
// ============================================================
__global__ void __launch_bounds__(256, 2)
vq_main(const float* __restrict__ z_e,
        const float* __restrict__ emb,
        float* __restrict__ out) {
    extern __shared__ float sm[];
    float* z_s = sm;                    // [256][ZPITCH]
    float* e_s = sm + CDIM * ZPITCH;    // [CT][KT]
    __shared__ int   idx_s[BN];
    __shared__ float lred[8];

    const int tid = threadIdx.x;
    const int n0  = blockIdx.x * BN;
    const int b0  = n0 >> 10;
    const int hw0 = n0 & 1023;
    const float* zin = z_e + (size_t)b0 * CDIM * HW + hw0;

    // ---- load z tile [c][n], coalesced 256B segments ----
    {
        int i = tid & 63, cq = tid >> 6;
        #pragma unroll 4
        for (int cc = 0; cc < CDIM; cc += 4) {
            int c = cc + cq;
            z_s[c * ZPITCH + i] = zin[(size_t)c * HW + i];
        }
    }
    __syncthreads();

    const int tx = tid & 31;   // k: tx*8 .. tx*8+7 within chunk
    const int ty = tid >> 5;   // n: ty*8 .. ty*8+7

    float bval[8];
    int   bidx[8];
    #pragma unroll
    for (int i = 0; i < 8; i++) { bval[i] = 3.4e38f; bidx[i] = 0; }

    for (int k0 = 0; k0 < KCODES; k0 += KT) {
        unsigned long long acc[8][4];
        #pragma unroll
        for (int n = 0; n < 8; n++)
            #pragma unroll
            for (int kp = 0; kp < 4; kp++) acc[n][kp] = 0ull;

        for (int c0 = 0; c0 < CDIM; c0 += CT) {
            __syncthreads();
            // load e tile [CT][KT]
            {
                int col = (tid & 63) << 2;
                int r0  = tid >> 6;
                #pragma unroll
                for (int j = 0; j < CT; j += 4) {
                    int r = r0 + j;
                    *(float4*)&e_s[r * KT + col] =
                        *(const float4*)&g_eT[(size_t)(c0 + r) * KCODES + k0 + col];
                }
            }
            __syncthreads();

            #pragma unroll 8
            for (int c = 0; c < CT; c++) {
                const float* zr = &z_s[(c0 + c) * ZPITCH + ty * 8];
                float4 za = *(const float4*)zr;          // broadcast within warp
                float4 zb = *(const float4*)(zr + 4);
                const ulonglong2* er =
                    (const ulonglong2*)&e_s[c * KT + tx * 8];
                ulonglong2 E0 = er[0];
                ulonglong2 E1 = er[1];
                float zarr[8] = {za.x, za.y, za.z, za.w, zb.x, zb.y, zb.z, zb.w};
                #pragma unroll
                for (int n = 0; n < 8; n++) {
                    unsigned long long a = packdup(zarr[n]);
                    ffma2(acc[n][0], a, E0.x);
                    ffma2(acc[n][1], a, E0.y);
                    ffma2(acc[n][2], a, E1.x);
                    ffma2(acc[n][3], a, E1.y);
                }
            }
        }

        // ---- score + argmin update for this k chunk ----
        float4 en0 = *(const float4*)&g_enorm[k0 + tx * 8];
        float4 en1 = *(const float4*)&g_enorm[k0 + tx * 8 + 4];
        float en[8] = {en0.x, en0.y, en0.z, en0.w, en1.x, en1.y, en1.z, en1.w};
        #pragma unroll
        for (int n = 0; n < 8; n++) {
            #pragma unroll
            for (int kp = 0; kp < 4; kp++) {
                float d0, d1;
                unpack2(acc[n][kp], d0, d1);
                int kk = k0 + tx * 8 + kp * 2;
                float s0 = en[kp * 2]     - 2.0f * d0;
                float s1 = en[kp * 2 + 1] - 2.0f * d1;
                if (s0 < bval[n]) { bval[n] = s0; bidx[n] = kk; }
                if (s1 < bval[n]) { bval[n] = s1; bidx[n] = kk + 1; }
            }
        }
    }

    // ---- warp (32 lanes = all k for this ty) argmin reduction ----
    #pragma unroll
    for (int n = 0; n < 8; n++) {
        float v = bval[n]; int ix = bidx[n];
        #pragma unroll
        for (int o = 16; o; o >>= 1) {
            float v2 = __shfl_xor_sync(~0u, v, o);
            int   i2 = __shfl_xor_sync(~0u, ix, o);
            if (v2 < v || (v2 == v && i2 < ix)) { v = v2; ix = i2; }
        }
        if (tx == 0) idx_s[ty * 8 + n] = ix;
    }
    __syncthreads();

    if (tid < BN) out[O_TOK + n0 + tid] = (float)idx_s[tid];

    // ---- phase 2: loss partials, dw scatter, stage q into z_s ----
    float lacc = 0.0f;
    for (int nl = 0; nl < BN; nl++) {
        int ix = idx_s[nl];
        float q  = __ldg(&emb[ix * CDIM + tid]);
        float zv = z_s[tid * ZPITCH + nl];
        float d  = q - zv;
        lacc += d * d;
        atomicAdd(&g_dw[ix * CDIM + tid], zv);
        z_s[tid * ZPITCH + nl] = q;     // overwrite with quantized
    }
    if (tid < BN) atomicAdd(&g_counts[idx_s[tid]], 1.0f);

    #pragma unroll
    for (int o = 16; o; o >>= 1) lacc += __shfl_xor_sync(~0u, lacc, o);
    if ((tid & 31) == 0) lred[tid >> 5] = lacc;
    __syncthreads();
    if (tid == 0) {
        float s = 0.f;
        #pragma unroll
        for (int i = 0; i < 8; i++) s += lred[i];
        atomicAdd(&g_loss, s);
    }
    __syncthreads();

    // ---- phase 3: coalesced q_out store [B,C,H,W] ----
    {
        int nn = tid & 63, cq = tid >> 6;
        float* outq = out + O_Q + (size_t)b0 * CDIM * HW + hw0;
        #pragma unroll 4
        for (int cc = 0; cc < CDIM; cc += 4) {
            int c = cc + cq;
            outq[(size_t)c * HW + nn] = z_s[c * ZPITCH + nn];
        }
    }
}

// ============================================================
// K2a: cluster-size EMA + normalizers + loss/perplexity. 1 x 1024
// ============================================================
__global__ void vq_final_a(const float* __restrict__ ema_cs,
                           float* __restrict__ out) {
    int t = threadIdx.x;
    __shared__ float s1[32], s2[32];
    float cnt = g_counts[t];
    float ncs = ema_cs[t] * 0.99f + 0.01f * cnt;
    out[O_NCS + t] = ncs;
    float p  = cnt * (1.0f / 32768.0f);
    float pl = p * logf(p + 1e-10f);

    float a = ncs, b = pl;
    #pragma unroll
    for (int o = 16; o; o >>= 1) {
        a += __shfl_xor_sync(~0u, a, o);
        b += __shfl_xor_sync(~0u, b, o);
    }
    if ((t & 31) == 0) { s1[t >> 5] = a; s2[t >> 5] = b; }
    __syncthreads();
    if (t < 32) {
        float a2 = s1[t], b2 = s2[t];
        #pragma unroll
        for (int o = 16; o; o >>= 1) {
            a2 += __shfl_xor_sync(~0u, a2, o);
            b2 += __shfl_xor_sync(~0u, b2, o);
        }
        if (t == 0) { s1[0] = a2; s2[0] = b2; }
    }
    __syncthreads();
    float nsum = s1[0];
    if (t == 0) {
        out[O_PERP] = expf(-s2[0]);
        out[O_LOSS] = 0.25f * g_loss * (1.0f / 8388608.0f);
    }
    float cs = (ncs + 1e-10f) / (nsum + 1024.0f * 1e-10f) * nsum;
    g_invcs[t] = 1.0f / cs;
}

// ============================================================
// K2b: new_ema_w + new_embedding.  grid 256 x 256.
// float4 loads (aligned device arrays), float2 stores to out
// (out indices are EVEN but not mult-of-4 -> only 8B alignment).
// ============================================================
__global__ void vq_final_b(const float* __restrict__ ema_w,
                           float* __restrict__ out) {
    int i = (blockIdx.x * 256 + threadIdx.x) * 4;   // < 262144
    float4 w  = *(const float4*)&ema_w[i];
    float4 dw = *(const float4*)&g_dw[i];
    float4 nw;
    nw.x = w.x * 0.99f + 0.01f * dw.x;
    nw.y = w.y * 0.99f + 0.01f * dw.y;
    nw.z = w.z * 0.99f + 0.01f * dw.z;
    nw.w = w.w * 0.99f + 0.01f * dw.w;
    float2 w01 = {nw.x, nw.y}, w23 = {nw.z, nw.w};
    *(float2*)&out[O_NEW_W + i]     = w01;
    *(float2*)&out[O_NEW_W + i + 2] = w23;
    float ic = g_invcs[i >> 8];
    float2 e01 = {nw.x * ic, nw.y * ic}, e23 = {nw.z * ic, nw.w * ic};
    *(float2*)&out[O_NEW_E + i]     = e01;
    *(float2*)&out[O_NEW_E + i + 2] = e23;
}

// ============================================================
extern "C" void kernel_launch(void* const* d_in, const int* in_sizes, int n_in,
                              void* d_out, int out_size) {
    const float* z_e    = (const float*)d_in[0];
    const float* emb    = (const float*)d_in[1];
    const float* ema_cs = (const float*)d_in[2];
    const float* ema_w  = (const float*)d_in[3];
    float* out = (float*)d_out;

    const int smem_bytes = (CDIM * ZPITCH + CT * KT) * sizeof(float); // 102400
    cudaFuncSetAttribute(vq_main, cudaFuncAttributeMaxDynamicSharedMemorySize,
                         smem_bytes);

    vq_prep<<<KCODES, 256>>>(emb);
    vq_main<<<NTOT / BN, 256, smem_bytes>>>(z_e, emb, out);
    vq_final_a<<<1, 1024>>>(ema_cs, out);
    vq_final_b<<<256, 256>>>(ema_w, out);
}